// round 14
// baseline (speedup 1.0000x reference)
#include <cuda_runtime.h>
#include <cuda_bf16.h>
#include <mma.h>
#include <stdint.h>

using namespace nvcuda;

#define NBATCH 4096
#define NN 64
#define NH 8
#define NL 3
#define TPB 128
#define BPC 4            // batches per CTA
#define PLD 72           // P row stride (bf16)
#define SLD 36           // Sarr column stride (float)
#define XLD 9            // xs row stride

// P rows: r = b*6 + p, p: 0=x_hi, 1=x_lo, 2=x^2, 3=x^3, 4=x^4, 5=ones (-> S0)
// rows 24..31 = zero padding (tile-clean); C[32,64] = P @ Mask,
// Sarr[n*SLD + r] = C[r][n] (col-major store); only r<24 consumed.

__global__ void __launch_bounds__(TPB)
cat_wmma(const float* __restrict__ X, const int* __restrict__ dag,
         const float* __restrict__ Wk, const float* __restrict__ Wq,
         const float* __restrict__ Wv, const float* __restrict__ Wp,
         const float* __restrict__ bp, const float* __restrict__ W1,
         const float* __restrict__ b1, const float* __restrict__ W2,
         const float* __restrict__ b2, const float* __restrict__ Wlm,
         const float* __restrict__ blm, float* __restrict__ out)
{
    __shared__ __align__(32) __nv_bfloat16 Mk[64 * 64];   // Mk[m*64+n] = dag[m][n] != 0
    __shared__ __align__(32) __nv_bfloat16 Pm[32 * PLD];
    __shared__ __align__(32) float         Sarr[64 * SLD];
    __shared__ float  xs[64 * XLD];                        // xs[m*XLD + b]
    __shared__ float2 scg[NL * NH];                        // (ch, gh)
    __shared__ float  smlp[NL * 14];
    __shared__ float  slm[2];

    const int tid = threadIdx.x;
    const int w   = tid >> 5;
    const size_t base = (size_t)blockIdx.x * BPC * 64;

    // ---- stage X (coalesced) ----
    #pragma unroll
    for (int i = tid; i < BPC * 64; i += TPB)
        xs[(i & 63) * XLD + (i >> 6)] = X[base + i];

    // ---- mask -> bf16 (scalar loads; no alignment assumptions on dag) ----
    #pragma unroll 4
    for (int i = tid; i < 64 * 64; i += TPB)
        Mk[i] = __float2bfloat16((dag[i] != 0) ? 1.f : 0.f);

    // ---- zero P pad rows 24..31 (once; only rows <24 rewritten per layer) ----
    for (int i = tid; i < 8 * PLD; i += TPB)
        Pm[24 * PLD + i] = __float2bfloat16(0.f);

    // ---- weight contractions ----
    if (tid < NL * NH) {
        const int l = tid >> 3, h = tid & 7;
        const float* q = Wq + tid * 16;
        const float* k = Wk + tid * 16;
        float s = 0.f;
        #pragma unroll
        for (int d = 0; d < 16; d++) s = fmaf(q[d], k[d], s);
        const float* v = Wv + tid * 16;
        const float* p = Wp + l * 128 + h * 16;
        float g = 0.f;
        #pragma unroll
        for (int d = 0; d < 16; d++) g = fmaf(v[d], p[d], g);
        scg[tid] = make_float2(s * 0.25f, g);              // scale = HS^-0.5
    } else if (tid >= 32 && tid < 32 + NL) {
        const int l = tid - 32;
        smlp[l * 14 + 0] = bp[l];
        #pragma unroll
        for (int j = 0; j < 4; j++) {
            smlp[l * 14 + 1 + j] = W1[l * 4 + j];
            smlp[l * 14 + 5 + j] = b1[l * 4 + j];
            smlp[l * 14 + 9 + j] = W2[l * 4 + j];
        }
        smlp[l * 14 + 13] = b2[l];
    } else if (tid == 40) {
        slm[0] = Wlm[0]; slm[1] = blm[0];
    }
    __syncthreads();

    const __nv_bfloat16 ONE = __float2bfloat16(1.f);

    #pragma unroll 1
    for (int l = 0; l < NL; l++) {
        // ---- build P: thread -> (m = i>>2, b = i&3), writes 6 power rows ----
        #pragma unroll
        for (int i = tid; i < 64 * BPC; i += TPB) {
            const int m = i >> 2, b = i & 3;
            const float x = xs[m * XLD + b];
            const __nv_bfloat16 hx = __float2bfloat16(x);
            const float x2 = x * x;
            __nv_bfloat16* pr = &Pm[b * 6 * PLD + m];
            pr[0 * PLD] = hx;
            pr[1 * PLD] = __float2bfloat16(x - __bfloat162float(hx));
            pr[2 * PLD] = __float2bfloat16(x2);
            pr[3 * PLD] = __float2bfloat16(x2 * x);
            pr[4 * PLD] = __float2bfloat16(x2 * x2);
            pr[5 * PLD] = ONE;
        }
        __syncthreads();

        // ---- moments GEMM: C[32,64] = P @ Mask; 8 tiles over 4 warps ----
        for (int id = w; id < 8; id += 4) {
            const int rt = id >> 2, nt = id & 3;
            wmma::fragment<wmma::accumulator, 16, 16, 16, float> fc;
            wmma::fill_fragment(fc, 0.f);
            #pragma unroll
            for (int kt = 0; kt < 4; kt++) {
                wmma::fragment<wmma::matrix_a, 16, 16, 16, __nv_bfloat16, wmma::row_major> fa;
                wmma::fragment<wmma::matrix_b, 16, 16, 16, __nv_bfloat16, wmma::row_major> fb;
                wmma::load_matrix_sync(fa, Pm + rt * 16 * PLD + kt * 16, PLD);
                wmma::load_matrix_sync(fb, Mk + kt * 16 * 64 + nt * 16, 64);
                wmma::mma_sync(fc, fa, fb, fc);
            }
            wmma::store_matrix_sync(Sarr + nt * 16 * SLD + rt * 16, fc, SLD,
                                    wmma::mem_col_major);
        }
        __syncthreads();

        // ---- epilogue: thread -> (b = tid&3, ngrp = tid>>2); 2 rows each ----
        const float2* cgl = &scg[l * NH];
        const float*  ml  = &smlp[l * 14];
        const int b    = tid & 3;
        const int ngrp = tid >> 2;
        #pragma unroll 1
        for (int r = 0; r < 2; r++) {
            const int n = ngrp + r * 32;
            const float* sp = &Sarr[n * SLD + b * 6];
            const float S1 = sp[0] + sp[1];                // hi + lo
            const float S2 = sp[2];
            const float S3 = sp[3];
            const float S4 = sp[4];
            const float S0 = sp[5];                        // exact count from ones-row
            const float xn = xs[n * XLD + b];
            // deg-3 Taylor: se = S0 + t S1 + t^2/2 S2 + t^3/6 S3
            //               sx = S1 + t S2 + t^2/2 S3 + t^3/6 S4
            const float a2 = S2 * 0.5f, a3 = S3 * (1.f / 6.f);
            const float b2c = S3 * 0.5f, b3 = S4 * (1.f / 6.f);
            float delta = 0.f;
            #pragma unroll
            for (int h = 0; h < NH; h++) {
                const float2 cg = cgl[h];
                const float t = cg.x * xn;
                const float se = fmaf(fmaf(fmaf(a3, t, a2), t, S1), t, S0);
                const float sx = fmaf(fmaf(fmaf(b3, t, b2c), t, S2), t, S1);
                delta = fmaf(cg.y, __fdividef(sx, se), delta);
            }
            if (S0 == 0.f) delta = 0.f;                    // kill 0/0 (empty row)

            const float xv = xn + delta + ml[0];
            float acc = xv + ml[13];
            #pragma unroll
            for (int j = 0; j < 4; j++)
                acc = fmaf(fmaxf(fmaf(xv, ml[1 + j], ml[5 + j]), 0.f), ml[9 + j], acc);
            xs[n * XLD + b] = acc;                         // own cell only
        }
        __syncthreads();
    }

    // ---- output ----
    const float wlmv = slm[0], blmv = slm[1];
    #pragma unroll
    for (int i = tid; i < BPC * 64; i += TPB)
        out[base + i] = fmaf(xs[(i & 63) * XLD + (i >> 6)], wlmv, blmv);
}

// ---------------- launch: single kernel ----------------
extern "C" void kernel_launch(void* const* d_in, const int* in_sizes, int n_in,
                              void* d_out, int out_size)
{
    const float* X   = (const float*)d_in[0];
    const int*   dag = (const int*)  d_in[1];
    const float* Wk  = (const float*)d_in[2];
    const float* Wq  = (const float*)d_in[3];
    const float* Wv  = (const float*)d_in[4];
    const float* Wp  = (const float*)d_in[5];
    const float* bp  = (const float*)d_in[6];
    const float* W1  = (const float*)d_in[7];
    const float* b1  = (const float*)d_in[8];
    const float* W2  = (const float*)d_in[9];
    const float* b2  = (const float*)d_in[10];
    const float* Wlm = (const float*)d_in[11];
    const float* blm = (const float*)d_in[12];
    float* out = (float*)d_out;

    cat_wmma<<<NBATCH / BPC, TPB>>>(X, dag, Wk, Wq, Wv, Wp, bp, W1, b1, W2, b2,
                                    Wlm, blm, out);
}

// round 16
// speedup vs baseline: 1.0767x; 1.0767x over previous
#include <cuda_runtime.h>
#include <cuda_bf16.h>
#include <mma.h>
#include <stdint.h>

using namespace nvcuda;

#define NBATCH 4096
#define NN 64
#define NH 8
#define NL 3
#define TPB 128
#define BPC 4            // batches per CTA
#define PLD 72           // P row stride (bf16)
#define SRLD 72          // Sarr row stride (float, row-major [r][n])
#define XLD 9            // xs row stride

// ---- prep outputs (device globals; aligned) ----
__device__ __align__(16) __nv_bfloat16 g_mask[64 * 64];  // g_mask[m*64+n] = dag[m][n] != 0
__device__ float2 g_scg[NL * NH];                        // (ch, gh)
__device__ float  g_mlp[NL * 14];
__device__ float  g_lm[2];

// ---- prep kernel: mask bf16 conversion + weight contractions (once) ----
__global__ void prep_kernel(const int* __restrict__ dag,
                            const float* __restrict__ Wk, const float* __restrict__ Wq,
                            const float* __restrict__ Wv, const float* __restrict__ Wp,
                            const float* __restrict__ bp, const float* __restrict__ W1,
                            const float* __restrict__ b1, const float* __restrict__ W2,
                            const float* __restrict__ b2, const float* __restrict__ Wlm,
                            const float* __restrict__ blm)
{
    const int t = threadIdx.x;
    for (int i = t; i < 64 * 64; i += TPB)
        g_mask[i] = __float2bfloat16((dag[i] != 0) ? 1.f : 0.f);

    if (t < NL * NH) {
        const int l = t >> 3, h = t & 7;
        const float* q = Wq + t * 16;
        const float* k = Wk + t * 16;
        float s = 0.f;
        #pragma unroll
        for (int d = 0; d < 16; d++) s = fmaf(q[d], k[d], s);
        const float* v = Wv + t * 16;
        const float* p = Wp + l * 128 + h * 16;
        float g = 0.f;
        #pragma unroll
        for (int d = 0; d < 16; d++) g = fmaf(v[d], p[d], g);
        g_scg[t] = make_float2(s * 0.25f, g);            // scale = HS^-0.5
    } else if (t >= 32 && t < 32 + NL) {
        const int l = t - 32;
        g_mlp[l * 14 + 0] = bp[l];
        #pragma unroll
        for (int j = 0; j < 4; j++) {
            g_mlp[l * 14 + 1 + j] = W1[l * 4 + j];
            g_mlp[l * 14 + 5 + j] = b1[l * 4 + j];
            g_mlp[l * 14 + 9 + j] = W2[l * 4 + j];
        }
        g_mlp[l * 14 + 13] = b2[l];
    } else if (t == 40) {
        g_lm[0] = Wlm[0]; g_lm[1] = blm[0];
    }
}

// P rows: r = b*6 + p, p: 0=x_hi, 1=x_lo, 2=x^2, 3=x^3, 4=x^4, 5=ones (-> S0)
// rows 24..31 zero pad; C[32,64] = P @ Mask, stored ROW-major Sr[r][n], ld=SRLD.
__global__ void __launch_bounds__(TPB)
cat_wmma(const float* __restrict__ X, float* __restrict__ out)
{
    __shared__ __align__(32) __nv_bfloat16 Mk[64 * 64];
    __shared__ __align__(32) __nv_bfloat16 Pm[32 * PLD];
    __shared__ __align__(32) float         Sr[32 * SRLD];
    __shared__ float  xs[64 * XLD];                      // xs[n*XLD + b]
    __shared__ float2 scg[NL * NH];
    __shared__ float  smlp[NL * 14];
    __shared__ float  slm[2];

    const int tid = threadIdx.x;
    const int w   = tid >> 5;
    const size_t base = (size_t)blockIdx.x * BPC * 64;

    // ---- stage X (coalesced) ----
    #pragma unroll
    for (int i = tid; i < BPC * 64; i += TPB)
        xs[(i & 63) * XLD + (i >> 6)] = X[base + i];

    // ---- copy mask from prepped global via 64-bit loads (8B-aligned) ----
    {
        const uint2* src = (const uint2*)g_mask;
        uint2* dst = (uint2*)Mk;
        #pragma unroll
        for (int i = tid; i < (64 * 64 * 2) / 8; i += TPB)
            dst[i] = src[i];
    }

    // ---- copy contracted weights ----
    if (tid < NL * NH) scg[tid] = g_scg[tid];
    if (tid >= 64 && tid < 64 + NL * 14) smlp[tid - 64] = g_mlp[tid - 64];
    if (tid >= 120 && tid < 122) slm[tid - 120] = g_lm[tid - 120];

    // ---- zero P pad rows 24..31 (once) ----
    for (int i = tid; i < 8 * PLD; i += TPB)
        Pm[24 * PLD + i] = __float2bfloat16(0.f);
    __syncthreads();

    const __nv_bfloat16 ONE = __float2bfloat16(1.f);
    const int n_ep  = tid & 63;          // epilogue: lane-contiguous n
    const int bh_ep = tid >> 6;          // 0 or 1 -> b = bh*2 + r

    #pragma unroll 1
    for (int l = 0; l < NL; l++) {
        // ---- build P: thread -> (m = i>>2, b = i&3), writes 6 power rows ----
        #pragma unroll
        for (int i = tid; i < 64 * BPC; i += TPB) {
            const int m = i >> 2, b = i & 3;
            const float x = xs[m * XLD + b];
            const __nv_bfloat16 hx = __float2bfloat16(x);
            const float x2 = x * x;
            __nv_bfloat16* pr = &Pm[b * 6 * PLD + m];
            pr[0 * PLD] = hx;
            pr[1 * PLD] = __float2bfloat16(x - __bfloat162float(hx));
            pr[2 * PLD] = __float2bfloat16(x2);
            pr[3 * PLD] = __float2bfloat16(x2 * x);
            pr[4 * PLD] = __float2bfloat16(x2 * x2);
            pr[5 * PLD] = ONE;
        }
        __syncthreads();

        // ---- moments GEMM: C[32,64] = P @ Mask; 8 tiles over 4 warps ----
        for (int id = w; id < 8; id += 4) {
            const int rt = id >> 2, nt = id & 3;
            wmma::fragment<wmma::accumulator, 16, 16, 16, float> fc;
            wmma::fill_fragment(fc, 0.f);
            #pragma unroll
            for (int kt = 0; kt < 4; kt++) {
                wmma::fragment<wmma::matrix_a, 16, 16, 16, __nv_bfloat16, wmma::row_major> fa;
                wmma::fragment<wmma::matrix_b, 16, 16, 16, __nv_bfloat16, wmma::row_major> fb;
                wmma::load_matrix_sync(fa, Pm + rt * 16 * PLD + kt * 16, PLD);
                wmma::load_matrix_sync(fb, Mk + kt * 16 * 64 + nt * 16, 64);
                wmma::mma_sync(fc, fa, fb, fc);
            }
            wmma::store_matrix_sync(Sr + rt * 16 * SRLD + nt * 16, fc, SRLD,
                                    wmma::mem_row_major);
        }
        __syncthreads();

        // ---- epilogue: thread -> (n = tid&63, b = (tid>>6)*2 + r); 2 cells each ----
        const float2* cgl = &scg[l * NH];
        const float*  ml  = &smlp[l * 14];
        #pragma unroll 1
        for (int r = 0; r < 2; r++) {
            const int b = bh_ep * 2 + r;
            const float* sp = &Sr[b * 6 * SRLD + n_ep];    // 6 rows, stride SRLD
            const float S1 = sp[0] + sp[SRLD];             // hi + lo
            const float S2 = sp[2 * SRLD];
            const float S3 = sp[3 * SRLD];
            const float S4 = sp[4 * SRLD];
            const float S0 = sp[5 * SRLD];                 // exact count (ones-row)
            const float xn = xs[n_ep * XLD + b];
            // deg-3 Taylor: se = S0 + t S1 + t^2/2 S2 + t^3/6 S3
            //               sx = S1 + t S2 + t^2/2 S3 + t^3/6 S4
            const float a2 = S2 * 0.5f, a3 = S3 * (1.f / 6.f);
            const float b2c = S3 * 0.5f, b3 = S4 * (1.f / 6.f);
            float delta = 0.f;
            #pragma unroll
            for (int h = 0; h < NH; h++) {
                const float2 cg = cgl[h];
                const float t = cg.x * xn;
                const float se = fmaf(fmaf(fmaf(a3, t, a2), t, S1), t, S0);
                const float sx = fmaf(fmaf(fmaf(b3, t, b2c), t, S2), t, S1);
                delta = fmaf(cg.y, __fdividef(sx, se), delta);
            }
            if (S0 == 0.f) delta = 0.f;                    // kill 0/0 (empty row)

            const float xv = xn + delta + ml[0];
            float acc = xv + ml[13];
            #pragma unroll
            for (int j = 0; j < 4; j++)
                acc = fmaf(fmaxf(fmaf(xv, ml[1 + j], ml[5 + j]), 0.f), ml[9 + j], acc);
            xs[n_ep * XLD + b] = acc;                      // own cell only
        }
        __syncthreads();
    }

    // ---- output ----
    const float wlmv = slm[0], blmv = slm[1];
    #pragma unroll
    for (int i = tid; i < BPC * 64; i += TPB)
        out[base + i] = fmaf(xs[(i & 63) * XLD + (i >> 6)], wlmv, blmv);
}

// ---------------- launch: prep + main ----------------
extern "C" void kernel_launch(void* const* d_in, const int* in_sizes, int n_in,
                              void* d_out, int out_size)
{
    const float* X   = (const float*)d_in[0];
    const int*   dag = (const int*)  d_in[1];
    const float* Wk  = (const float*)d_in[2];
    const float* Wq  = (const float*)d_in[3];
    const float* Wv  = (const float*)d_in[4];
    const float* Wp  = (const float*)d_in[5];
    const float* bp  = (const float*)d_in[6];
    const float* W1  = (const float*)d_in[7];
    const float* b1  = (const float*)d_in[8];
    const float* W2  = (const float*)d_in[9];
    const float* b2  = (const float*)d_in[10];
    const float* Wlm = (const float*)d_in[11];
    const float* blm = (const float*)d_in[12];
    float* out = (float*)d_out;

    prep_kernel<<<1, TPB>>>(dag, Wk, Wq, Wv, Wp, bp, W1, b1, W2, b2, Wlm, blm);
    cat_wmma<<<NBATCH / BPC, TPB>>>(X, out);
}